// round 9
// baseline (speedup 1.0000x reference)
#include <cuda_runtime.h>
#include <cuda_fp16.h>
#include <cstdint>
#include <cstdio>

// ---------------------------------------------------------------------------
// MoE top-1 layer — guaranteed-correct SIMT fp32 path + diagnostics.
// router -> scatter/gather(fp32) -> SIMT GEMM1 (relu+b1) -> SIMT GEMM2
// (bias+weight scatter). Weights read in native [k][n] layout (no transpose
// needed). Probe kernel tests mma.sync and the transpose kernel, printf's.
// ---------------------------------------------------------------------------

#define T_TOK   16384
#define DM      1024
#define DFF     4096
#define NE      8
#define BM      128
#define BN      128
#define BK      16
#define MAX_MT  136
#define PADCAP  (MAX_MT * BM)

// ------------------------------- scratch -----------------------------------
__device__ float g_Xg32[(size_t)PADCAP * DM];     // gathered tokens (fp32)
__device__ float g_Hg32[(size_t)PADCAP * DFF];    // hidden after relu (fp32)
__device__ __half g_W1T[(size_t)NE * DFF * DM];   // probe target only
__device__ int   g_expert[T_TOK];
__device__ float g_wtok[T_TOK];
__device__ int   g_counts[NE];
__device__ int   g_cursor[NE];
__device__ int   g_segstart[NE];
__device__ int   g_pos[T_TOK];
__device__ int   g_gtok[PADCAP];
__device__ int   g_tile_e[MAX_MT];
__device__ int   g_tile_m0[MAX_MT];
__device__ float g_probe[8];

#define MMA16816(d, a, b) \
    asm volatile("mma.sync.aligned.m16n8k16.row.col.f32.f16.f16.f32 " \
                 "{%0,%1,%2,%3}, {%4,%5,%6,%7}, {%8,%9}, {%0,%1,%2,%3};" \
                 : "+f"((d)[0]), "+f"((d)[1]), "+f"((d)[2]), "+f"((d)[3]) \
                 : "r"((a)[0]), "r"((a)[1]), "r"((a)[2]), "r"((a)[3]), \
                   "r"((b)[0]), "r"((b)[1]))

// ------------------------------- kernels -----------------------------------

__global__ void init_kernel() {
    if (threadIdx.x < NE) g_counts[threadIdx.x] = 0;
}

__global__ void router_kernel(const float* __restrict__ x,
                              const float* __restrict__ Wr,
                              const float* __restrict__ br) {
    int warp = (blockIdx.x * blockDim.x + threadIdx.x) >> 5;
    int lane = threadIdx.x & 31;
    if (warp >= T_TOK) return;
    const float* xr = x + (size_t)warp * DM;
    float acc[NE];
#pragma unroll
    for (int e = 0; e < NE; e++) acc[e] = 0.f;
    for (int i = lane; i < DM; i += 32) {
        float xv = xr[i];
        const float* w = Wr + (size_t)i * NE;
#pragma unroll
        for (int e = 0; e < NE; e++) acc[e] = fmaf(xv, w[e], acc[e]);
    }
#pragma unroll
    for (int off = 16; off; off >>= 1)
#pragma unroll
        for (int e = 0; e < NE; e++)
            acc[e] += __shfl_xor_sync(0xffffffffu, acc[e], off);
    if (lane == 0) {
        float m = -1e30f; int be = 0;
#pragma unroll
        for (int e = 0; e < NE; e++) {
            float l = acc[e] + br[e];
            acc[e] = l;
            if (l > m) { m = l; be = e; }
        }
        float s = 0.f;
#pragma unroll
        for (int e = 0; e < NE; e++) s += expf(acc[e] - m);
        g_expert[warp] = be;
        g_wtok[warp]   = 1.0f / s;
        atomicAdd(&g_counts[be], 1);
    }
}

__global__ void plan_kernel() {
    if (threadIdx.x != 0) return;
    int off = 0, nt = 0;
    for (int e = 0; e < NE; e++) {
        g_segstart[e] = off;
        g_cursor[e]   = off;
        int c = g_counts[e];
        int ntile = (c + BM - 1) / BM;
        for (int i = 0; i < ntile; i++) {
            g_tile_e[nt]  = e;
            g_tile_m0[nt] = off + i * BM;
            nt++;
        }
        off += ntile * BM;
    }
    for (int i = nt; i < MAX_MT; i++) g_tile_e[i] = -1;
}

__global__ void scatter_pos_kernel() {
    int t = blockIdx.x * blockDim.x + threadIdx.x;
    if (t >= T_TOK) return;
    int e = g_expert[t];
    int p = atomicAdd(&g_cursor[e], 1);
    g_pos[t] = p;
    g_gtok[p] = t;
}

// Gather fp32 rows into expert-sorted order. Also zero the padded tail rows
// once per launch (deterministic: pad rows depend only on routing).
__global__ void gather_x_kernel(const float* __restrict__ x) {
    int t = blockIdx.x;
    int p = g_pos[t];
    const float4* src = (const float4*)(x + (size_t)t * DM);
    float4* dst = (float4*)(g_Xg32 + (size_t)p * DM);
    for (int i = threadIdx.x; i < DM / 4; i += blockDim.x)
        dst[i] = src[i];
}
__global__ void zero_pad_kernel() {   // zero any padded rows of g_Xg32
    int nt = 0;
    // recompute padded extent cheaply per block
    __shared__ int s_tot;
    if (threadIdx.x == 0) {
        int off = 0;
        for (int e = 0; e < NE; e++)
            off += ((g_counts[e] + BM - 1) / BM) * BM;
        s_tot = off;
    }
    __syncthreads();
    nt = s_tot;
    // rows in [token-valid region ends per expert handled via gtok check]:
    // simpler: zero rows whose g_gtok entry was never written this launch is
    // not detectable, so instead zero rows >= segstart[e]+counts[e] within
    // each padded expert segment.
    for (int e = 0; e < NE; e++) {
        int s0 = g_segstart[e], c = g_counts[e];
        int pad_end = s0 + ((c + BM - 1) / BM) * BM;
        for (int r = s0 + c + blockIdx.x; r < pad_end; r += gridDim.x) {
            float4* dst = (float4*)(g_Xg32 + (size_t)r * DM);
            for (int i = threadIdx.x; i < DM / 4; i += blockDim.x)
                dst[i] = make_float4(0.f, 0.f, 0.f, 0.f);
        }
    }
    (void)nt;
}

// Transpose-convert (PROBE TARGET ONLY): fp32 [E][R][C] -> fp16 [E][C][R]
__global__ void transpose_convert_kernel(const float* __restrict__ src,
                                         __half* __restrict__ dst,
                                         int R, int C) {
    __shared__ float tile[32][33];
    int e = blockIdx.z;
    int c0 = blockIdx.x * 32, r0 = blockIdx.y * 32;
    const float* s = src + (size_t)e * R * C;
    __half* d = dst + (size_t)e * R * C;
#pragma unroll
    for (int i = threadIdx.y; i < 32; i += 8)
        tile[i][threadIdx.x] = s[(size_t)(r0 + i) * C + c0 + threadIdx.x];
    __syncthreads();
#pragma unroll
    for (int i = threadIdx.y; i < 32; i += 8)
        d[(size_t)(c0 + i) * R + r0 + threadIdx.x] =
            __float2half_rn(tile[threadIdx.x][i]);
}

// --------------------------- SIMT fp32 GEMM --------------------------------
// C[m][n] = sum_k A[m][k] * B[k][n];  A: [rows][KTOT], B: W[e] native [KTOT][NTOT]
// MODE 1: Hg32 = relu(A@B + b1);  MODE 2: out[tok] = (A@B + b2) * wtok
template <int KTOT, int NTOT, int MODE>
__global__ __launch_bounds__(256)
void moe_gemm_simt(const float* __restrict__ W, const float* __restrict__ bias,
                   float* __restrict__ outp) {
    int ti = blockIdx.y;
    int e  = g_tile_e[ti];
    if (e < 0) return;
    int m0 = g_tile_m0[ti];
    int n0 = blockIdx.x * BN;

    __shared__ float sAT[BK][BM + 4];    // A transposed: [k][m]
    __shared__ float sB[BK][BN];         // B: [k][n]

    int tid = threadIdx.x;
    int rm  = tid >> 4;                  // 0..15 -> rows rm*8..rm*8+7
    int cn  = tid & 15;                  // 0..15 -> cols cn*8..cn*8+7

    const float* Agl = ((MODE == 1) ? g_Xg32 : g_Hg32) + (size_t)m0 * KTOT;
    const float* Bgl = W + (size_t)e * KTOT * NTOT + n0;

    // per-thread load slots
    int ar[2], ac[2], brr[2], bc[2];
#pragma unroll
    for (int j = 0; j < 2; j++) {
        int idx = j * 256 + tid;
        ar[j] = idx >> 2;  ac[j] = idx & 3;      // A: 128 rows x 4 float4
        brr[j] = idx >> 5; bc[j] = idx & 31;     // B: 16 rows x 32 float4
    }

    float acc[8][8];
#pragma unroll
    for (int i = 0; i < 8; i++)
#pragma unroll
        for (int j = 0; j < 8; j++) acc[i][j] = 0.f;

    const int NKB = KTOT / BK;
    float4 pa[2], pb[2];

    // preload k-block 0
#pragma unroll
    for (int j = 0; j < 2; j++) {
        pa[j] = *(const float4*)(Agl + (size_t)ar[j] * KTOT + ac[j] * 4);
        pb[j] = *(const float4*)(Bgl + (size_t)brr[j] * NTOT + bc[j] * 4);
    }
#pragma unroll
    for (int j = 0; j < 2; j++) {
        sAT[ac[j] * 4 + 0][ar[j]] = pa[j].x;
        sAT[ac[j] * 4 + 1][ar[j]] = pa[j].y;
        sAT[ac[j] * 4 + 2][ar[j]] = pa[j].z;
        sAT[ac[j] * 4 + 3][ar[j]] = pa[j].w;
        *(float4*)&sB[brr[j]][bc[j] * 4] = pb[j];
    }
    __syncthreads();

    for (int kb = 0; kb < NKB; kb++) {
        if (kb + 1 < NKB) {
            const float* An = Agl + (kb + 1) * BK;
            const float* Bn = Bgl + (size_t)(kb + 1) * BK * NTOT;
#pragma unroll
            for (int j = 0; j < 2; j++) {
                pa[j] = *(const float4*)(An + (size_t)ar[j] * KTOT + ac[j] * 4);
                pb[j] = *(const float4*)(Bn + (size_t)brr[j] * NTOT + bc[j] * 4);
            }
        }
#pragma unroll
        for (int kk = 0; kk < BK; kk++) {
            float a[8], b[8];
            *(float4*)&a[0] = *(const float4*)&sAT[kk][rm * 8];
            *(float4*)&a[4] = *(const float4*)&sAT[kk][rm * 8 + 4];
            *(float4*)&b[0] = *(const float4*)&sB[kk][cn * 8];
            *(float4*)&b[4] = *(const float4*)&sB[kk][cn * 8 + 4];
#pragma unroll
            for (int i = 0; i < 8; i++)
#pragma unroll
                for (int j = 0; j < 8; j++)
                    acc[i][j] = fmaf(a[i], b[j], acc[i][j]);
        }
        __syncthreads();
        if (kb + 1 < NKB) {
#pragma unroll
            for (int j = 0; j < 2; j++) {
                sAT[ac[j] * 4 + 0][ar[j]] = pa[j].x;
                sAT[ac[j] * 4 + 1][ar[j]] = pa[j].y;
                sAT[ac[j] * 4 + 2][ar[j]] = pa[j].z;
                sAT[ac[j] * 4 + 3][ar[j]] = pa[j].w;
                *(float4*)&sB[brr[j]][bc[j] * 4] = pb[j];
            }
            __syncthreads();
        }
    }

    // ------------------------------ epilogue -------------------------------
    if (MODE == 1) {
        const float* bg = bias + (size_t)e * DFF + n0 + cn * 8;
        float bv[8];
#pragma unroll
        for (int j = 0; j < 8; j++) bv[j] = bg[j];
#pragma unroll
        for (int i = 0; i < 8; i++) {
            float* drow = g_Hg32 + (size_t)(m0 + rm * 8 + i) * DFF + n0 + cn * 8;
            float4 v0, v1;
            v0.x = fmaxf(acc[i][0] + bv[0], 0.f);
            v0.y = fmaxf(acc[i][1] + bv[1], 0.f);
            v0.z = fmaxf(acc[i][2] + bv[2], 0.f);
            v0.w = fmaxf(acc[i][3] + bv[3], 0.f);
            v1.x = fmaxf(acc[i][4] + bv[4], 0.f);
            v1.y = fmaxf(acc[i][5] + bv[5], 0.f);
            v1.z = fmaxf(acc[i][6] + bv[6], 0.f);
            v1.w = fmaxf(acc[i][7] + bv[7], 0.f);
            *(float4*)(drow)     = v0;
            *(float4*)(drow + 4) = v1;
        }
    } else {
        const float* bg = bias + (size_t)e * DM + n0 + cn * 8;
        float bv[8];
#pragma unroll
        for (int j = 0; j < 8; j++) bv[j] = bg[j];
        int seg0 = g_segstart[e], cnt = g_counts[e];
#pragma unroll
        for (int i = 0; i < 8; i++) {
            int gr = m0 + rm * 8 + i;
            if ((gr - seg0) < cnt) {
                int tok = g_gtok[gr];
                float w = g_wtok[tok];
                float* orow = outp + (size_t)tok * DM + n0 + cn * 8;
                float4 v0, v1;
                v0.x = (acc[i][0] + bv[0]) * w;
                v0.y = (acc[i][1] + bv[1]) * w;
                v0.z = (acc[i][2] + bv[2]) * w;
                v0.w = (acc[i][3] + bv[3]) * w;
                v1.x = (acc[i][4] + bv[4]) * w;
                v1.y = (acc[i][5] + bv[5]) * w;
                v1.z = (acc[i][6] + bv[6]) * w;
                v1.w = (acc[i][7] + bv[7]) * w;
                *(float4*)(orow)     = v0;
                *(float4*)(orow + 4) = v1;
            }
        }
    }
}

// --------------------------- diagnostic probe ------------------------------
// One warp: (1) mma.sync on known smem halves vs SIMT reference,
//           (2) transpose spot check. Prints once per replay.
__global__ void probe_kernel(const float* __restrict__ W1) {
    __shared__ __half A[16][16];   // [m][k]
    __shared__ __half B[8][16];    // [n][k]  (col-major B = B^T storage)
    int lane = threadIdx.x;
    if (lane == 0) {
        for (int m = 0; m < 16; m++)
            for (int k = 0; k < 16; k++)
                A[m][k] = __float2half((float)((m * 3 + k) % 7) - 3.0f);
        for (int n = 0; n < 8; n++)
            for (int k = 0; k < 16; k++)
                B[n][k] = __float2half((float)((n * 5 + k) % 5) - 2.0f);
    }
    __syncwarp();
    uint32_t a[4], b[2];
    float d[4] = {0.f, 0.f, 0.f, 0.f};
    int r = lane >> 2, c = lane & 3;
    a[0] = *(const uint32_t*)&A[r][2 * c];
    a[1] = *(const uint32_t*)&A[r + 8][2 * c];
    a[2] = *(const uint32_t*)&A[r][2 * c + 8];
    a[3] = *(const uint32_t*)&A[r + 8][2 * c + 8];
    b[0] = *(const uint32_t*)&B[r][2 * c];      // n = lane>>2? NO: spec n=lane/4
    b[1] = *(const uint32_t*)&B[r][2 * c + 8];  // B[n=lane/4][k=2*(lane%4)(+8)]
    MMA16816(d, a, b);
    __syncwarp();
    if (lane == 0) {
        // reference for c0: row m=0, col n=0: sum_k A[0][k]*B[0][k]
        float ref = 0.f;
        for (int k = 0; k < 16; k++)
            ref += __half2float(A[0][k]) * __half2float(B[0][k]);
        float got = d[0];
        float tgot = __half2float(g_W1T[(size_t)37 * DM + 11]);
        float twant = W1[(size_t)11 * DFF + 37];
        g_probe[0] = got; g_probe[1] = ref;
        g_probe[2] = tgot; g_probe[3] = twant;
        printf("PROBE mma_got=%f mma_ref=%f trans_got=%f trans_want=%f\n",
               got, ref, tgot, twant);
    }
}

// ------------------------------ launcher -----------------------------------
extern "C" void kernel_launch(void* const* d_in, const int* in_sizes, int n_in,
                              void* d_out, int out_size) {
    const float* x  = (const float*)d_in[0];
    const float* Wr = (const float*)d_in[1];
    const float* br = (const float*)d_in[2];
    const float* W1 = (const float*)d_in[3];
    const float* b1 = (const float*)d_in[4];
    const float* W2 = (const float*)d_in[5];
    const float* b2 = (const float*)d_in[6];
    float* out = (float*)d_out;
    (void)in_sizes; (void)n_in; (void)out_size;

    init_kernel<<<1, 32>>>();
    router_kernel<<<T_TOK / 8, 256>>>(x, Wr, br);
    plan_kernel<<<1, 32>>>();
    scatter_pos_kernel<<<T_TOK / 256, 256>>>();
    gather_x_kernel<<<T_TOK, 128>>>(x);
    zero_pad_kernel<<<64, 128>>>();

    // GEMM1: A=g_Xg32 [*, DM], B=W1[e] [DM][DFF] -> Hg32 (relu + b1)
    moe_gemm_simt<DM, DFF, 1><<<dim3(DFF / BN, MAX_MT), 256>>>(W1, b1, nullptr);
    // GEMM2: A=g_Hg32 [*, DFF], B=W2[e] [DFF][DM] -> out (bias + weight, scatter)
    moe_gemm_simt<DFF, DM, 2><<<dim3(DM / BN, MAX_MT), 256>>>(W2, b2, out);

    // Diagnostics (tiny): transpose W1 -> g_W1T, then probe mma + transpose.
    transpose_convert_kernel<<<dim3(DFF / 32, DM / 32, NE), dim3(32, 8)>>>(W1, g_W1T, DM, DFF);
    probe_kernel<<<1, 32>>>(W1);
}